// round 1
// baseline (speedup 1.0000x reference)
#include <cuda_runtime.h>
#include <cuda_bf16.h>

// Problem constants (fixed by the dataset)
#define NRAYS   8192
#define KSEL    4096
#define KSPLIT  64
#define CHUNK   (KSEL / KSPLIT)   // 64 k per block
#define TPB     256
#define NPT     4                 // n's per thread
#define NBLK    (NRAYS / (TPB * NPT))  // 8 n-tile blocks

// Scratch (no allocations allowed)
__device__ __align__(16) float g_coef[KSEL * 16];        // 256 KB
__device__ float g_partial[KSPLIT * NRAYS];              // 2 MB

// s = sqrt(0.5 * log2(e)) : folds exp(-0.5 q) -> 2^(-||W d||^2)
#define SCALE_S 0.8493281132464818f

// ---------------------------------------------------------------------------
// Kernel 1: per selected gaussian, compute W = s * L^{-1} (lower-tri 4x4),
// c = W * mu, pack [W(10), c(4), label, pad] into g_coef[k*16..]
// ---------------------------------------------------------------------------
__global__ void setup_kernel(const float* __restrict__ emb,
                             const float* __restrict__ chol,
                             const float* __restrict__ labels,
                             const int*   __restrict__ idx)
{
    int k = blockIdx.x * blockDim.x + threadIdx.x;
    if (k >= KSEL) return;
    int m = idx[k];
    const float* Lp = chol + (size_t)m * 16;
    float L00 = Lp[0];
    float L10 = Lp[4],  L11 = Lp[5];
    float L20 = Lp[8],  L21 = Lp[9],  L22 = Lp[10];
    float L30 = Lp[12], L31 = Lp[13], L32 = Lp[14], L33 = Lp[15];

    float i0 = 1.0f / L00, i1 = 1.0f / L11, i2 = 1.0f / L22, i3 = 1.0f / L33;

    float U00 = i0;
    float U11 = i1;
    float U22 = i2;
    float U33 = i3;
    float U10 = -(L10 * U00) * i1;
    float U20 = -(L20 * U00 + L21 * U10) * i2;
    float U21 = -(L21 * U11) * i2;
    float U30 = -(L30 * U00 + L31 * U10 + L32 * U20) * i3;
    float U31 = -(L31 * U11 + L32 * U21) * i3;
    float U32 = -(L32 * U22) * i3;

    const float s = SCALE_S;
    U00 *= s; U10 *= s; U11 *= s; U20 *= s; U21 *= s; U22 *= s;
    U30 *= s; U31 *= s; U32 *= s; U33 *= s;

    const float* mp = emb + (size_t)m * 4;
    float m0 = mp[0], m1 = mp[1], m2 = mp[2], m3 = mp[3];
    float c0 = U00 * m0;
    float c1 = U10 * m0 + U11 * m1;
    float c2 = U20 * m0 + U21 * m1 + U22 * m2;
    float c3 = U30 * m0 + U31 * m1 + U32 * m2 + U33 * m3;

    float lab = labels[m];

    float* o = g_coef + (size_t)k * 16;
    o[0]  = U00; o[1]  = U10; o[2]  = U11; o[3]  = U20;
    o[4]  = U21; o[5]  = U22; o[6]  = U30; o[7]  = U31;
    o[8]  = U32; o[9]  = U33; o[10] = c0;  o[11] = c1;
    o[12] = c2;  o[13] = c3;  o[14] = lab; o[15] = 0.0f;
}

// ---------------------------------------------------------------------------
// Kernel 2: main. grid = (NBLK, KSPLIT). Each block: CHUNK k's from shared,
// NPT rays per thread. partial[ksplit][n] = sum over chunk of lab*2^(-||y||^2)
// ---------------------------------------------------------------------------
__global__ void __launch_bounds__(TPB)
main_kernel(const float* __restrict__ org,
            const float* __restrict__ dir,
            float* __restrict__ partial)
{
    __shared__ float4 sm[CHUNK * 4];

    int tid   = threadIdx.x;
    int nbase = blockIdx.x * (TPB * NPT);
    int kbase = blockIdx.y * CHUNK;

    // stage chunk coefficients (CHUNK*4 float4 = 256 -> one per thread)
    const float4* gsrc = reinterpret_cast<const float4*>(g_coef) + (size_t)kbase * 4;
    sm[tid] = gsrc[tid];

    // load NPT ray positions
    float p0[NPT], p1[NPT], p2[NPT], p3[NPT], acc[NPT];
    const float2* o2 = reinterpret_cast<const float2*>(org);
    const float2* d2 = reinterpret_cast<const float2*>(dir);
#pragma unroll
    for (int j = 0; j < NPT; j++) {
        int n = nbase + tid + j * TPB;
        float2 o = o2[n];
        float2 d = d2[n];
        p0[j] = o.x; p1[j] = o.y; p2[j] = d.x; p3[j] = d.y;
        acc[j] = 0.0f;
    }
    __syncthreads();

#pragma unroll 4
    for (int kk = 0; kk < CHUNK; kk++) {
        float4 f0 = sm[kk * 4 + 0];   // U00 U10 U11 U20
        float4 f1 = sm[kk * 4 + 1];   // U21 U22 U30 U31
        float4 f2 = sm[kk * 4 + 2];   // U32 U33 c0  c1
        float4 f3 = sm[kk * 4 + 3];   // c2  c3  lab pad
#pragma unroll
        for (int j = 0; j < NPT; j++) {
            float y0 = __fmaf_rn(f0.x, p0[j], -f2.z);
            float y1 = __fmaf_rn(f0.y, p0[j], -f2.w);
            y1 = __fmaf_rn(f0.z, p1[j], y1);
            float y2 = __fmaf_rn(f0.w, p0[j], -f3.x);
            y2 = __fmaf_rn(f1.x, p1[j], y2);
            y2 = __fmaf_rn(f1.y, p2[j], y2);
            float y3 = __fmaf_rn(f1.z, p0[j], -f3.y);
            y3 = __fmaf_rn(f1.w, p1[j], y3);
            y3 = __fmaf_rn(f2.x, p2[j], y3);
            y3 = __fmaf_rn(f2.y, p3[j], y3);
            // negated squared norm (negation folds into FFMA operand)
            float qn = -(y0 * y0);
            qn = __fmaf_rn(y1, -y1, qn);
            qn = __fmaf_rn(y2, -y2, qn);
            qn = __fmaf_rn(y3, -y3, qn);
            float e;
            asm("ex2.approx.ftz.f32 %0, %1;" : "=f"(e) : "f"(qn));
            acc[j] = __fmaf_rn(f3.z, e, acc[j]);
        }
    }

    float* pout = partial + (size_t)blockIdx.y * NRAYS + nbase;
#pragma unroll
    for (int j = 0; j < NPT; j++)
        pout[tid + j * TPB] = acc[j];
}

// ---------------------------------------------------------------------------
// Kernel 3: reduce split-K partials + sigmoid
// ---------------------------------------------------------------------------
__global__ void reduce_kernel(const float* __restrict__ partial,
                              float* __restrict__ out)
{
    int n = blockIdx.x * blockDim.x + threadIdx.x;
    if (n >= NRAYS) return;
    float s = 0.0f;
#pragma unroll
    for (int i = 0; i < KSPLIT; i++)
        s += partial[(size_t)i * NRAYS + n];
    // sigmoid(s) = 1 / (1 + 2^(-s*log2 e))
    float t = -s * 1.4426950408889634f;
    float e;
    asm("ex2.approx.ftz.f32 %0, %1;" : "=f"(e) : "f"(t));
    out[n] = 1.0f / (1.0f + e);
}

// ---------------------------------------------------------------------------
extern "C" void kernel_launch(void* const* d_in, const int* in_sizes, int n_in,
                              void* d_out, int out_size)
{
    const float* origins    = (const float*)d_in[0];
    const float* directions = (const float*)d_in[1];
    const float* embeddings = (const float*)d_in[2];
    const float* chol       = (const float*)d_in[3];
    const float* labels     = (const float*)d_in[4];
    const int*   idx        = (const int*)  d_in[5];
    float* out = (float*)d_out;

    float* coef_ptr = nullptr;
    float* part_ptr = nullptr;
    cudaGetSymbolAddress((void**)&coef_ptr, g_coef);
    cudaGetSymbolAddress((void**)&part_ptr, g_partial);
    (void)coef_ptr;

    setup_kernel<<<(KSEL + TPB - 1) / TPB, TPB>>>(embeddings, chol, labels, idx);
    main_kernel<<<dim3(NBLK, KSPLIT), TPB>>>(origins, directions, part_ptr);
    reduce_kernel<<<(NRAYS + TPB - 1) / TPB, TPB>>>(part_ptr, out);
}

// round 2
// speedup vs baseline: 1.0645x; 1.0645x over previous
#include <cuda_runtime.h>
#include <cuda_bf16.h>

typedef unsigned long long u64;

// Problem constants (fixed by the dataset)
#define NRAYS   8192
#define KSEL    4096
#define KSPLIT  64
#define CHUNK   (KSEL / KSPLIT)        // 64 gaussians per block column
#define TPB     128
#define NPT     8                      // rays per thread (4 f32x2 pairs)
#define NPAIR   (NPT / 2)
#define NBLK    (NRAYS / (TPB * NPT))  // 8 n-tile blocks

// Scratch (no allocations allowed)
__device__ float g_partial[KSPLIT * NRAYS];   // 2 MB

// s = sqrt(0.5 * log2(e)) : folds exp(-0.5 q) -> 2^(-||W d||^2)
#define SCALE_S 0.8493281132464818f

// ---- packed f32x2 helpers -------------------------------------------------
#define FMA2(d, a, b, c) \
    asm("fma.rn.f32x2 %0, %1, %2, %3;" : "=l"(d) : "l"(a), "l"(b), "l"(c))
#define MUL2(d, a, b) \
    asm("mul.rn.f32x2 %0, %1, %2;" : "=l"(d) : "l"(a), "l"(b))

__device__ __forceinline__ u64 pack2(float lo, float hi) {
    u64 r;
    asm("mov.b64 %0, {%1, %2};" : "=l"(r) : "r"(__float_as_uint(lo)), "r"(__float_as_uint(hi)));
    return r;
}
__device__ __forceinline__ void unpack2(u64 v, float& lo, float& hi) {
    unsigned a, b;
    asm("mov.b64 {%0, %1}, %2;" : "=r"(a), "=r"(b) : "l"(v));
    lo = __uint_as_float(a); hi = __uint_as_float(b);
}
__device__ __forceinline__ u64 dup2(float x) {
    u64 r;
    asm("mov.b64 %0, {%1, %1};" : "=l"(r) : "r"(__float_as_uint(x)));
    return r;
}
__device__ __forceinline__ float ex2_neg(float q) {
    // 2^(-q): sign flip via LOP3 (ALU pipe), then MUFU.EX2
    float nq = __uint_as_float(__float_as_uint(q) ^ 0x80000000u);
    float e;
    asm("ex2.approx.ftz.f32 %0, %1;" : "=f"(e) : "f"(nq));
    return e;
}

// ---------------------------------------------------------------------------
// Fused kernel: grid = (NBLK, KSPLIT).
// Phase 1 (threads 0..CHUNK-1): gather gaussian k, compute W = s*L^{-1},
//   nc = -(W*mu), store DUPLICATED f32x2 coefficients into shared.
// Phase 2 (all threads): 8 rays/thread as 4 f32x2 pairs, FFMA2 mainloop.
// ---------------------------------------------------------------------------
__global__ void __launch_bounds__(TPB)
fused_kernel(const float* __restrict__ org,
             const float* __restrict__ dir,
             const float* __restrict__ emb,
             const float* __restrict__ chol,
             const float* __restrict__ labels,
             const int*   __restrict__ idx,
             float* __restrict__ partial)
{
    __shared__ u64 smc[CHUNK * 16];   // 8 KB, coefficients duplicated per lane

    const int tid   = threadIdx.x;
    const int nbase = blockIdx.x * (TPB * NPT);
    const int kbase = blockIdx.y * CHUNK;

    // ---- Phase 1: per-gaussian setup (threads 0..63) ----
    if (tid < CHUNK) {
        int k = kbase + tid;
        int m = __ldg(idx + k);
        const float4* c4 = reinterpret_cast<const float4*>(chol) + (size_t)m * 4;
        float4 r0 = c4[0], r1 = c4[1], r2 = c4[2], r3 = c4[3];
        float L00 = r0.x;
        float L10 = r1.x, L11 = r1.y;
        float L20 = r2.x, L21 = r2.y, L22 = r2.z;
        float L30 = r3.x, L31 = r3.y, L32 = r3.z, L33 = r3.w;

        float i0 = 1.0f / L00, i1 = 1.0f / L11, i2 = 1.0f / L22, i3 = 1.0f / L33;

        float U00 = i0;
        float U11 = i1;
        float U22 = i2;
        float U33 = i3;
        float U10 = -(L10 * U00) * i1;
        float U20 = -(L20 * U00 + L21 * U10) * i2;
        float U21 = -(L21 * U11) * i2;
        float U30 = -(L30 * U00 + L31 * U10 + L32 * U20) * i3;
        float U31 = -(L31 * U11 + L32 * U21) * i3;
        float U32 = -(L32 * U22) * i3;

        const float s = SCALE_S;
        U00 *= s; U10 *= s; U11 *= s; U20 *= s; U21 *= s; U22 *= s;
        U30 *= s; U31 *= s; U32 *= s; U33 *= s;

        float4 mu = reinterpret_cast<const float4*>(emb)[m];
        float nc0 = -(U00 * mu.x);
        float nc1 = -(U10 * mu.x + U11 * mu.y);
        float nc2 = -(U20 * mu.x + U21 * mu.y + U22 * mu.z);
        float nc3 = -(U30 * mu.x + U31 * mu.y + U32 * mu.z + U33 * mu.w);

        float lab = __ldg(labels + m);

        u64* o = smc + tid * 16;
        o[0]  = dup2(U00); o[1]  = dup2(U10); o[2]  = dup2(U11); o[3]  = dup2(U20);
        o[4]  = dup2(U21); o[5]  = dup2(U22); o[6]  = dup2(U30); o[7]  = dup2(U31);
        o[8]  = dup2(U32); o[9]  = dup2(U33); o[10] = dup2(nc0); o[11] = dup2(nc1);
        o[12] = dup2(nc2); o[13] = dup2(nc3); o[14] = dup2(lab); o[15] = 0ull;
    }

    // ---- load rays (independent of shared) ----
    u64 P0[NPAIR], P1[NPAIR], P2[NPAIR], P3[NPAIR], ACC[NPAIR];
    const float2* o2 = reinterpret_cast<const float2*>(org);
    const float2* d2 = reinterpret_cast<const float2*>(dir);
#pragma unroll
    for (int j = 0; j < NPAIR; j++) {
        int na = nbase + tid + (2 * j) * TPB;
        int nb = nbase + tid + (2 * j + 1) * TPB;
        float2 oa = o2[na], ob = o2[nb];
        float2 da = d2[na], db = d2[nb];
        P0[j] = pack2(oa.x, ob.x);
        P1[j] = pack2(oa.y, ob.y);
        P2[j] = pack2(da.x, db.x);
        P3[j] = pack2(da.y, db.y);
        ACC[j] = 0ull;
    }
    __syncthreads();

    // ---- Phase 2: FFMA2 mainloop ----
#pragma unroll 2
    for (int kk = 0; kk < CHUNK; kk++) {
        const ulonglong2* cp = reinterpret_cast<const ulonglong2*>(smc + kk * 16);
        ulonglong2 a0 = cp[0], a1 = cp[1], a2 = cp[2], a3 = cp[3];
        ulonglong2 a4 = cp[4], a5 = cp[5], a6 = cp[6], a7 = cp[7];
        u64 W00 = a0.x, W10 = a0.y, W11 = a1.x, W20 = a1.y;
        u64 W21 = a2.x, W22 = a2.y, W30 = a3.x, W31 = a3.y;
        u64 W32 = a4.x, W33 = a4.y, NC0 = a5.x, NC1 = a5.y;
        u64 NC2 = a6.x, NC3 = a6.y, LAB = a7.x;

#pragma unroll
        for (int j = 0; j < NPAIR; j++) {
            u64 y0, y1, y2, y3, q;
            FMA2(y0, W00, P0[j], NC0);
            FMA2(y1, W10, P0[j], NC1);
            FMA2(y1, W11, P1[j], y1);
            FMA2(y2, W20, P0[j], NC2);
            FMA2(y2, W21, P1[j], y2);
            FMA2(y2, W22, P2[j], y2);
            FMA2(y3, W30, P0[j], NC3);
            FMA2(y3, W31, P1[j], y3);
            FMA2(y3, W32, P2[j], y3);
            FMA2(y3, W33, P3[j], y3);
            MUL2(q, y0, y0);
            FMA2(q, y1, y1, q);
            FMA2(q, y2, y2, q);
            FMA2(q, y3, y3, q);
            float ql, qh;
            unpack2(q, ql, qh);
            float el = ex2_neg(ql);
            float eh = ex2_neg(qh);
            u64 e2 = pack2(el, eh);
            FMA2(ACC[j], LAB, e2, ACC[j]);
        }
    }

    float* pout = partial + (size_t)blockIdx.y * NRAYS + nbase;
#pragma unroll
    for (int j = 0; j < NPAIR; j++) {
        float al, ah;
        unpack2(ACC[j], al, ah);
        pout[tid + (2 * j) * TPB]     = al;
        pout[tid + (2 * j + 1) * TPB] = ah;
    }
}

// ---------------------------------------------------------------------------
// Reduce split-K partials + sigmoid
// ---------------------------------------------------------------------------
__global__ void reduce_kernel(const float* __restrict__ partial,
                              float* __restrict__ out)
{
    int n = blockIdx.x * blockDim.x + threadIdx.x;
    if (n >= NRAYS) return;
    float s = 0.0f;
#pragma unroll
    for (int i = 0; i < KSPLIT; i++)
        s += partial[(size_t)i * NRAYS + n];
    // sigmoid(s) = 1 / (1 + 2^(-s*log2 e))
    float t = s * 1.4426950408889634f;
    float e = ex2_neg(t);
    out[n] = 1.0f / (1.0f + e);
}

// ---------------------------------------------------------------------------
extern "C" void kernel_launch(void* const* d_in, const int* in_sizes, int n_in,
                              void* d_out, int out_size)
{
    const float* origins    = (const float*)d_in[0];
    const float* directions = (const float*)d_in[1];
    const float* embeddings = (const float*)d_in[2];
    const float* chol       = (const float*)d_in[3];
    const float* labels     = (const float*)d_in[4];
    const int*   idx        = (const int*)  d_in[5];
    float* out = (float*)d_out;

    float* part_ptr = nullptr;
    cudaGetSymbolAddress((void**)&part_ptr, g_partial);

    fused_kernel<<<dim3(NBLK, KSPLIT), TPB>>>(origins, directions, embeddings,
                                              chol, labels, idx, part_ptr);
    reduce_kernel<<<(NRAYS + 255) / 256, 256>>>(part_ptr, out);
}